// round 14
// baseline (speedup 1.0000x reference)
#include <cuda_runtime.h>
#include <cstdint>

// Problem constants
constexpr int KC = 5, PC = 2, BC = 2, NC = 8, HC = 512, WC = 512;

// Full-width tiles: 4 rows x 512 cols, Blackwell 256-bit vector loads:
// each thread produces 8 consecutive outputs; every core access is
// ld.global.cs.v8.f32 -> 1024B contiguous per warp-instruction, half the
// LDG count / L1tex queue entries per byte vs float4.
constexpr int TH = 4;
constexpr int SWP = 520;             // padded row pitch (floats), 16B aligned
constexpr int NT = 256;              // threads per CTA (4 rows x 64 groups of 8)
constexpr int TILES_Y = HC / TH;     // 128 row-tiles
constexpr int N_TILES = TILES_Y * BC * NC;   // 2048
constexpr int GRID = 608;            // 152 SM x 4 CTAs, persistent
constexpr int SH = TH + 2 * PC;      // 8 staged rows
constexpr int SBUF = SH * SWP;       // 4160 floats per buffer

// cp.async 4B with zero-fill when !ok (src-size 0 -> no global read, zeros)
__device__ __forceinline__ void cp4(uint32_t dst, const float* src, bool ok) {
    asm volatile("cp.async.ca.shared.global [%0], [%1], 4, %2;\n"
                 :: "r"(dst), "l"(src), "r"(ok ? 4 : 0));
}

// 256-bit streaming global load (sm_100+)
__device__ __forceinline__ void ldg_cs_v8(float v[8], const float* p) {
    asm volatile("ld.global.cs.v8.f32 {%0,%1,%2,%3,%4,%5,%6,%7}, [%8];"
                 : "=f"(v[0]), "=f"(v[1]), "=f"(v[2]), "=f"(v[3]),
                   "=f"(v[4]), "=f"(v[5]), "=f"(v[6]), "=f"(v[7])
                 : "l"(p));
}

// 256-bit streaming global store (sm_100+)
__device__ __forceinline__ void stg_cs_v8(float* p, const float v[8]) {
    asm volatile("st.global.cs.v8.f32 [%0], {%1,%2,%3,%4,%5,%6,%7,%8};"
                 :: "l"(p),
                    "f"(v[0]), "f"(v[1]), "f"(v[2]), "f"(v[3]),
                    "f"(v[4]), "f"(v[5]), "f"(v[6]), "f"(v[7])
                 : "memory");
}

__global__ __launch_bounds__(NT, 4)
void kconv_kernel(const float* __restrict__ frames,
                  const float* __restrict__ core,
                  const float* __restrict__ Wt,
                  float* __restrict__ out)
{
    __shared__ float s[2][SBUF];

    const size_t plane = (size_t)HC * WC;
    const uint32_t sbase = (uint32_t)__cvta_generic_to_shared(&s[0][0]);

    // ---- async stage of one padded 8x520 frame strip into a smem buffer ----
    auto stage = [&](int t, int buf) {
        const int ty = (t & (TILES_Y - 1)) * TH;
        const int z  = t >> 7;                      // b*N + n
        const float* fb = frames + (size_t)z * plane;
        const uint32_t sb = sbase + (uint32_t)buf * (SBUF * 4);
        #pragma unroll
        for (int it = 0; it < 17; ++it) {
            const int idx = threadIdx.x + it * NT;
            if (idx < SBUF) {
                const int r = idx / SWP;
                const int c = idx - r * SWP;
                const int gy = ty + r - PC;
                const int gx = c - PC;
                const bool ok = (unsigned)gy < (unsigned)HC && (unsigned)gx < (unsigned)WC;
                const float* gp = ok ? (fb + (size_t)gy * WC + gx) : fb;
                cp4(sb + (uint32_t)idx * 4, gp, ok);
            }
        }
        asm volatile("cp.async.commit_group;\n");
    };

    // Thread -> output mapping: 4 rows x 64 groups of 8 floats.
    const int row = threadIdx.x >> 6;            // 0..3
    const int xg  = (threadIdx.x & 63) << 3;     // 0..504 (32B aligned)

    int t = blockIdx.x;
    if (t >= N_TILES) return;
    stage(t, 0);
    int buf = 0;

    while (t < N_TILES) {
        const int tn = t + GRID;                 // static strided schedule

        // make current buffer visible, then prefetch the next tile into the
        // other buffer (overlaps the compute below)
        asm volatile("cp.async.wait_group 0;\n");
        __syncthreads();
        if (tn < N_TILES) stage(tn, buf ^ 1);

        // ---- compute current tile ----
        const int ty = (t & (TILES_Y - 1)) * TH;
        const int z  = t >> 7;
        const int gy = ty + row;
        const size_t pix = (size_t)gy * WC + xg;

        const float* cbase = core + (size_t)z * (KC * KC) * plane;
        const float* wbase = Wt  + (size_t)z * plane;
        float*       obase = out + (size_t)z * plane;

        // W: read-once, issue early so its latency overlaps the core burst
        float wv[8];
        ldg_cs_v8(wv, wbase + pix);

        const float* sb = &s[buf][0];
        float acc[8];
        #pragma unroll
        for (int m = 0; m < 8; ++m) acc[m] = 0.f;

        // Per i: load the 12-float window row (3 aligned LDS.128), then a
        // pure burst of 5 x (v8 core load + 8 FMA).
        #pragma unroll
        for (int i = 0; i < KC; ++i) {
            const float* srow = sb + (row + i) * SWP + xg;
            const float4 a = *reinterpret_cast<const float4*>(srow);
            const float4 b = *reinterpret_cast<const float4*>(srow + 4);
            const float4 c = *reinterpret_cast<const float4*>(srow + 8);
            const float w[12] = { a.x, a.y, a.z, a.w,
                                  b.x, b.y, b.z, b.w,
                                  c.x, c.y, c.z, c.w };
            #pragma unroll
            for (int j = 0; j < KC; ++j) {
                const int k = i * KC + j;
                float cv[8];
                ldg_cs_v8(cv, cbase + (size_t)k * plane + pix);
                #pragma unroll
                for (int m = 0; m < 8; ++m)
                    acc[m] = fmaf(cv[m], w[j + m], acc[m]);
            }
        }

        float o[8];
        #pragma unroll
        for (int m = 0; m < 8; ++m) o[m] = acc[m] * wv[m];
        stg_cs_v8(obase + pix, o);

        t = tn;
        buf ^= 1;
    }
}

extern "C" void kernel_launch(void* const* d_in, const int* in_sizes, int n_in,
                              void* d_out, int out_size)
{
    const float* frames = (const float*)d_in[0];
    const float* core   = (const float*)d_in[1];
    const float* Wt     = (const float*)d_in[2];
    float* out          = (float*)d_out;

    kconv_kernel<<<GRID, NT>>>(frames, core, Wt, out);
}

// round 15
// speedup vs baseline: 1.0790x; 1.0790x over previous
#include <cuda_runtime.h>
#include <cstdint>

// Problem constants
constexpr int KC = 5, PC = 2, BC = 2, NC = 8, HC = 512, WC = 512;

// CHAMPION (R9): Full-width tiles, 4 rows x 512 cols. Each core-plane read
// per tile is one CONTIGUOUS 8KB block (4 rows x 2KB) -> maximal DRAM page
// locality for the 25 read-once core streams. Persistent CTAs with a static
// strided schedule, cp.async double-buffered frame staging, register-resident
// 5x8 window, __ldcs streaming reads, __stcs streaming store.
// Measured: 68.1us timed (~6.9 TB/s effective, 86% of HBM spec).
constexpr int TH = 4;
constexpr int SWP = 520;             // padded row pitch (floats), 16B aligned
constexpr int NT = 512;              // threads per CTA
constexpr int TILES_Y = HC / TH;     // 128 row-tiles
constexpr int N_TILES = TILES_Y * BC * NC;   // 2048
constexpr int GRID = 304;            // 152 SM x 2 CTAs, persistent
constexpr int SH = TH + 2 * PC;      // 8 staged rows
constexpr int SBUF = SH * SWP;       // 4160 floats per buffer

// cp.async 4B with zero-fill when !ok (src-size 0 -> no global read, zeros)
__device__ __forceinline__ void cp4(uint32_t dst, const float* src, bool ok) {
    asm volatile("cp.async.ca.shared.global [%0], [%1], 4, %2;\n"
                 :: "r"(dst), "l"(src), "r"(ok ? 4 : 0));
}

__global__ __launch_bounds__(NT, 2)
void kconv_kernel(const float* __restrict__ frames,
                  const float* __restrict__ core,
                  const float* __restrict__ Wt,
                  float* __restrict__ out)
{
    __shared__ float s[2][SBUF];

    const size_t plane = (size_t)HC * WC;
    const uint32_t sbase = (uint32_t)__cvta_generic_to_shared(&s[0][0]);

    // ---- async stage of one padded 8x520 frame strip into a smem buffer ----
    auto stage = [&](int t, int buf) {
        const int ty = (t & (TILES_Y - 1)) * TH;
        const int z  = t >> 7;                      // b*N + n
        const float* fb = frames + (size_t)z * plane;
        const uint32_t sb = sbase + (uint32_t)buf * (SBUF * 4);
        #pragma unroll
        for (int it = 0; it < 9; ++it) {
            const int idx = threadIdx.x + it * NT;
            if (idx < SH * SWP) {
                const int r = idx / SWP;
                const int c = idx - r * SWP;
                const int gy = ty + r - PC;
                const int gx = c - PC;
                const bool ok = (unsigned)gy < (unsigned)HC && (unsigned)gx < (unsigned)WC;
                const float* gp = ok ? (fb + (size_t)gy * WC + gx) : fb;
                cp4(sb + (uint32_t)idx * 4, gp, ok);
            }
        }
        asm volatile("cp.async.commit_group;\n");
    };

    // Thread -> output mapping: 4 rows x 128 float4-groups per tile.
    const int row = threadIdx.x >> 7;            // 0..3
    const int xx  = (threadIdx.x & 127) << 2;    // 0..508

    int t = blockIdx.x;
    if (t >= N_TILES) return;
    stage(t, 0);
    int buf = 0;

    while (t < N_TILES) {
        const int tn = t + GRID;                 // static strided schedule

        // make current buffer visible, then prefetch the next tile into the
        // other buffer (overlaps the compute below)
        asm volatile("cp.async.wait_group 0;\n");
        __syncthreads();
        if (tn < N_TILES) stage(tn, buf ^ 1);

        // ---- compute current tile ----
        const int ty = (t & (TILES_Y - 1)) * TH;
        const int z  = t >> 7;
        const int gy = ty + row;
        const size_t pix = (size_t)gy * WC + xx;

        const float* cbase = core + (size_t)z * (KC * KC) * plane;
        const float* wbase = Wt  + (size_t)z * plane;
        float*       obase = out + (size_t)z * plane;

        // W: read-once, issue early so its latency overlaps the core burst
        const float4 wv = __ldcs(reinterpret_cast<const float4*>(wbase + pix));

        // Preload the 5x8 frame window (pure LDS phase), then pure LDG->FMA.
        const float* sb = &s[buf][0];
        float w[KC][8];
        #pragma unroll
        for (int i = 0; i < KC; ++i) {
            const float* srow = sb + (row + i) * SWP + xx;
            const float4 a  = *reinterpret_cast<const float4*>(srow);
            const float4 bq = *reinterpret_cast<const float4*>(srow + 4);
            w[i][0] = a.x;  w[i][1] = a.y;  w[i][2] = a.z;  w[i][3] = a.w;
            w[i][4] = bq.x; w[i][5] = bq.y; w[i][6] = bq.z; w[i][7] = bq.w;
        }

        float acc0 = 0.f, acc1 = 0.f, acc2 = 0.f, acc3 = 0.f;
        #pragma unroll
        for (int i = 0; i < KC; ++i) {
            #pragma unroll
            for (int j = 0; j < KC; ++j) {
                const int k = i * KC + j;
                const float4 cv = __ldcs(
                    reinterpret_cast<const float4*>(cbase + (size_t)k * plane + pix));
                acc0 = fmaf(cv.x, w[i][j + 0], acc0);
                acc1 = fmaf(cv.y, w[i][j + 1], acc1);
                acc2 = fmaf(cv.z, w[i][j + 2], acc2);
                acc3 = fmaf(cv.w, w[i][j + 3], acc3);
            }
        }

        float4 o;
        o.x = acc0 * wv.x;
        o.y = acc1 * wv.y;
        o.z = acc2 * wv.z;
        o.w = acc3 * wv.w;
        __stcs(reinterpret_cast<float4*>(obase + pix), o);

        t = tn;
        buf ^= 1;
    }
}

extern "C" void kernel_launch(void* const* d_in, const int* in_sizes, int n_in,
                              void* d_out, int out_size)
{
    const float* frames = (const float*)d_in[0];
    const float* core   = (const float*)d_in[1];
    const float* Wt     = (const float*)d_in[2];
    float* out          = (float*)d_out;

    kconv_kernel<<<GRID, NT>>>(frames, core, Wt, out);
}

// round 16
// speedup vs baseline: 1.0912x; 1.0113x over previous
#include <cuda_runtime.h>
#include <cstdint>

// Problem constants
constexpr int KC = 5, PC = 2, BC = 2, NC = 8, HC = 512, WC = 512;

// FINAL CHAMPION (R9 design): Full-width tiles, 4 rows x 512 cols. Each
// core-plane read per tile is one CONTIGUOUS 8KB block (4 rows x 2KB) ->
// maximal DRAM page locality for the 25 read-once core streams. Persistent
// CTAs with a static strided schedule, cp.async double-buffered frame
// staging, register-resident 5x8 window, __ldcs streaming reads, __stcs
// streaming store. Measured best: 68.1us (~6.9 TB/s, 86% of HBM spec).
constexpr int TH = 4;
constexpr int SWP = 520;             // padded row pitch (floats), 16B aligned
constexpr int NT = 512;              // threads per CTA
constexpr int TILES_Y = HC / TH;     // 128 row-tiles
constexpr int N_TILES = TILES_Y * BC * NC;   // 2048
constexpr int GRID = 304;            // 152 SM x 2 CTAs, persistent
constexpr int SH = TH + 2 * PC;      // 8 staged rows
constexpr int SBUF = SH * SWP;       // 4160 floats per buffer

// cp.async 4B with zero-fill when !ok (src-size 0 -> no global read, zeros)
__device__ __forceinline__ void cp4(uint32_t dst, const float* src, bool ok) {
    asm volatile("cp.async.ca.shared.global [%0], [%1], 4, %2;\n"
                 :: "r"(dst), "l"(src), "r"(ok ? 4 : 0));
}

__global__ __launch_bounds__(NT, 2)
void kconv_kernel(const float* __restrict__ frames,
                  const float* __restrict__ core,
                  const float* __restrict__ Wt,
                  float* __restrict__ out)
{
    __shared__ float s[2][SBUF];

    const size_t plane = (size_t)HC * WC;
    const uint32_t sbase = (uint32_t)__cvta_generic_to_shared(&s[0][0]);

    // ---- async stage of one padded 8x520 frame strip into a smem buffer ----
    auto stage = [&](int t, int buf) {
        const int ty = (t & (TILES_Y - 1)) * TH;
        const int z  = t >> 7;                      // b*N + n
        const float* fb = frames + (size_t)z * plane;
        const uint32_t sb = sbase + (uint32_t)buf * (SBUF * 4);
        #pragma unroll
        for (int it = 0; it < 9; ++it) {
            const int idx = threadIdx.x + it * NT;
            if (idx < SH * SWP) {
                const int r = idx / SWP;
                const int c = idx - r * SWP;
                const int gy = ty + r - PC;
                const int gx = c - PC;
                const bool ok = (unsigned)gy < (unsigned)HC && (unsigned)gx < (unsigned)WC;
                const float* gp = ok ? (fb + (size_t)gy * WC + gx) : fb;
                cp4(sb + (uint32_t)idx * 4, gp, ok);
            }
        }
        asm volatile("cp.async.commit_group;\n");
    };

    // Thread -> output mapping: 4 rows x 128 float4-groups per tile.
    const int row = threadIdx.x >> 7;            // 0..3
    const int xx  = (threadIdx.x & 127) << 2;    // 0..508

    int t = blockIdx.x;
    if (t >= N_TILES) return;
    stage(t, 0);
    int buf = 0;

    while (t < N_TILES) {
        const int tn = t + GRID;                 // static strided schedule

        // make current buffer visible, then prefetch the next tile into the
        // other buffer (overlaps the compute below)
        asm volatile("cp.async.wait_group 0;\n");
        __syncthreads();
        if (tn < N_TILES) stage(tn, buf ^ 1);

        // ---- compute current tile ----
        const int ty = (t & (TILES_Y - 1)) * TH;
        const int z  = t >> 7;
        const int gy = ty + row;
        const size_t pix = (size_t)gy * WC + xx;

        const float* cbase = core + (size_t)z * (KC * KC) * plane;
        const float* wbase = Wt  + (size_t)z * plane;
        float*       obase = out + (size_t)z * plane;

        // W: read-once, issue early so its latency overlaps the core burst
        const float4 wv = __ldcs(reinterpret_cast<const float4*>(wbase + pix));

        // Preload the 5x8 frame window (pure LDS phase), then pure LDG->FMA.
        const float* sb = &s[buf][0];
        float w[KC][8];
        #pragma unroll
        for (int i = 0; i < KC; ++i) {
            const float* srow = sb + (row + i) * SWP + xx;
            const float4 a  = *reinterpret_cast<const float4*>(srow);
            const float4 bq = *reinterpret_cast<const float4*>(srow + 4);
            w[i][0] = a.x;  w[i][1] = a.y;  w[i][2] = a.z;  w[i][3] = a.w;
            w[i][4] = bq.x; w[i][5] = bq.y; w[i][6] = bq.z; w[i][7] = bq.w;
        }

        float acc0 = 0.f, acc1 = 0.f, acc2 = 0.f, acc3 = 0.f;
        #pragma unroll
        for (int i = 0; i < KC; ++i) {
            #pragma unroll
            for (int j = 0; j < KC; ++j) {
                const int k = i * KC + j;
                const float4 cv = __ldcs(
                    reinterpret_cast<const float4*>(cbase + (size_t)k * plane + pix));
                acc0 = fmaf(cv.x, w[i][j + 0], acc0);
                acc1 = fmaf(cv.y, w[i][j + 1], acc1);
                acc2 = fmaf(cv.z, w[i][j + 2], acc2);
                acc3 = fmaf(cv.w, w[i][j + 3], acc3);
            }
        }

        float4 o;
        o.x = acc0 * wv.x;
        o.y = acc1 * wv.y;
        o.z = acc2 * wv.z;
        o.w = acc3 * wv.w;
        __stcs(reinterpret_cast<float4*>(obase + pix), o);

        t = tn;
        buf ^= 1;
    }
}

extern "C" void kernel_launch(void* const* d_in, const int* in_sizes, int n_in,
                              void* d_out, int out_size)
{
    const float* frames = (const float*)d_in[0];
    const float* core   = (const float*)d_in[1];
    const float* Wt     = (const float*)d_in[2];
    float* out          = (float*)d_out;

    kconv_kernel<<<GRID, NT>>>(frames, core, Wt, out);
}